// round 6
// baseline (speedup 1.0000x reference)
#include <cuda_runtime.h>
#include <cuda_bf16.h>
#include <math.h>
#include <stdint.h>

#define NPTS   65536
#define CDIM   256
#define KCODES 2048

#define TH     256
#define NCH    16          // 2048 / 128
#define MARGIN 5e-4f
#define BIGF   3.4e38f

// ---- dynamic smem layout (bytes) ----
#define SA    0            // A tile: 128 rows x 512B (bf16, swizzled)
#define SB0   65536
#define SB1   131072
#define SBS   196608       // norms: 2048 f32
#define SAN   204800       // An: 128 f32
#define SMTOT 205312

// ---- device scratch ----
__device__ int      g_idx[NPTS];
__device__ float    g_cbn[KCODES];
__device__ uint32_t g_cbb[KCODES * 128];   // bf16x2-packed codebook
__device__ float    g_An[NPTS];
__device__ int      g_ccnt[NPTS];
__device__ int      g_cand[NPTS * 16];
__device__ int      g_cnt[KCODES];
__device__ double   g_loss;

// out layout (fp32): [z_q_st 16,777,216 | loss | perplexity | encodings]
#define OFF_LOSS 16777216
#define OFF_PERP 16777217
#define OFF_ENC  16777218

// ======================= helpers =======================
__device__ __forceinline__ uint32_t smem_u32(const void* p) {
    uint32_t a;
    asm("{ .reg .u64 t; cvta.to.shared.u64 t, %1; cvt.u32.u64 %0, t; }" : "=r"(a) : "l"(p));
    return a;
}
__device__ __forceinline__ uint32_t pack2(float a, float b) {
    __nv_bfloat162 t = __floats2bfloat162_rn(a, b);
    return *(uint32_t*)&t;
}
__device__ __forceinline__ void ldm4(uint32_t* r, uint32_t addr) {
    asm volatile("ldmatrix.sync.aligned.m8n8.x4.shared.b16 {%0,%1,%2,%3}, [%4];"
        : "=r"(r[0]), "=r"(r[1]), "=r"(r[2]), "=r"(r[3]) : "r"(addr));
}
__device__ __forceinline__ void mma16816(float* c, const uint32_t* a, const uint32_t* b) {
    asm volatile("mma.sync.aligned.m16n8k16.row.col.f32.bf16.bf16.f32 "
        "{%0,%1,%2,%3}, {%4,%5,%6,%7}, {%8,%9}, {%0,%1,%2,%3};"
        : "+f"(c[0]), "+f"(c[1]), "+f"(c[2]), "+f"(c[3])
        : "r"(a[0]), "r"(a[1]), "r"(a[2]), "r"(a[3]), "r"(b[0]), "r"(b[1]));
}

// ======================= prep: norms + bf16 codebook =======================
__global__ void k_prep(const float* __restrict__ cb) {
    int k = blockIdx.x * blockDim.x + threadIdx.x;
    if (k < KCODES) {
        const float* row = cb + (size_t)k * CDIM;
        float s = 0.f;
        #pragma unroll 8
        for (int c = 0; c < CDIM; ++c) {
            float t = row[c];
            s = __fadd_rn(s, __fmul_rn(t, t));
        }
        g_cbn[k] = s;
        g_cnt[k] = 0;
        #pragma unroll 4
        for (int p = 0; p < 128; ++p)
            g_cbb[(size_t)k * 128 + p] = pack2(row[2 * p], row[2 * p + 1]);
    }
    if (k == 0) g_loss = 0.0;
}

// ======================= HMMA distance GEMM + streaming argmin =======================
__global__ __launch_bounds__(TH, 1)
void k_argmin_mma(const float* __restrict__ z, const float* __restrict__ cb) {
    extern __shared__ char smem[];
    const uint32_t sb = smem_u32(smem);
    const int tid  = threadIdx.x;
    const int lane = tid & 31;
    const int wid  = tid >> 5;
    const int wm   = wid & 1;          // warp row (64 pts)
    const int wn   = wid >> 1;         // warp col (32 codes)

    const int blk = blockIdx.x;        // 0..511
    const int b   = blk >> 3;
    const int hw0 = (blk & 7) << 7;
    const int n0  = blk * 128;
    const float* zb = z + (size_t)b * (CDIM * 1024) + hw0;

    float* bsn = (float*)(smem + SBS);
    float* sAn = (float*)(smem + SAN);

    // ---- stage A (bf16 of z), swizzled [m][c] ----
    for (int it = 0; it < 64; ++it) {
        int e = tid + it * TH;          // 0..16383
        int m = e & 127, c = (e >> 7) << 1;
        float v0 = zb[(size_t)c * 1024 + m];
        float v1 = zb[(size_t)(c + 1) * 1024 + m];
        uint32_t off = (uint32_t)(m * 512 + ((((c >> 3) ^ (m & 7))) << 4) + (c & 7) * 2);
        *(uint32_t*)(smem + SA + off) = pack2(v0, v1);
    }
    // ---- norms to smem ----
    for (int j = tid; j < KCODES; j += TH) bsn[j] = g_cbn[j];

    // ---- An exact (reference rounding) ----
    if (tid < 128) {
        float p[32];
        #pragma unroll
        for (int l = 0; l < 32; ++l) p[l] = 0.f;
        #pragma unroll
        for (int i = 0; i < 8; ++i)
            #pragma unroll
            for (int l = 0; l < 32; ++l) {
                float t = zb[(size_t)(l + 32 * i) * 1024 + tid];
                p[l] = __fadd_rn(p[l], __fmul_rn(t, t));
            }
        #pragma unroll
        for (int off = 16; off >= 1; off >>= 1)
            #pragma unroll
            for (int l = 0; l < 16; ++l)
                if (l < off) p[l] = __fadd_rn(p[l], p[l + off]);
        sAn[tid] = p[0];
    }

    // ---- stage B chunk 0 ----
    for (int it = 0; it < 16; ++it) {
        int e = tid + it * TH;          // 0..4095
        int j = e >> 5, c8 = e & 31;
        uint4 v = *(const uint4*)&g_cbb[(size_t)j * 128 + c8 * 4];
        *(uint4*)(smem + SB0 + j * 512 + ((c8 ^ (j & 7)) << 4)) = v;
    }
    __syncthreads();

    // per-slot argmin state: slot s = tm*2 + half  (8 m-rows per thread)
    float best[8], cv[8];
    int   bk[8], ck[8];
    int   ovf = 0;
    float An_r[8];
    #pragma unroll
    for (int s = 0; s < 8; ++s) {
        best[s] = BIGF; cv[s] = BIGF; bk[s] = 0x7fffffff; ck[s] = 0x7fffffff;
        int tm = s >> 1, half = s & 1;
        An_r[s] = sAn[wm * 64 + tm * 16 + (lane >> 2) + half * 8];
    }

    const int pairc = (lane & 3) * 2;

    for (int i = 0; i < NCH; ++i) {
        const uint32_t sB = sb + ((i & 1) ? SB1 : SB0);

        // prefetch next chunk into the other buffer
        if (i + 1 < NCH) {
            const uint32_t dstb = ((i + 1) & 1) ? SB1 : SB0;   // byte offset into smem[]
            const int kb2 = (i + 1) * 128;
            #pragma unroll
            for (int it = 0; it < 16; ++it) {
                int e = tid + it * TH;
                int j = e >> 5, c8 = e & 31;
                uint4 v = *(const uint4*)&g_cbb[(size_t)(kb2 + j) * 128 + c8 * 4];
                *(uint4*)(smem + dstb + j * 512 + ((c8 ^ (j & 7)) << 4)) = v;
            }
        }

        float acc[4][4][4];
        #pragma unroll
        for (int tm = 0; tm < 4; ++tm)
            #pragma unroll
            for (int tn = 0; tn < 4; ++tn)
                #pragma unroll
                for (int r = 0; r < 4; ++r) acc[tm][tn][r] = 0.f;

        #pragma unroll
        for (int ks = 0; ks < 16; ++ks) {
            const int c0 = ks * 16;
            uint32_t a[4][4];
            #pragma unroll
            for (int tm = 0; tm < 4; ++tm) {
                int row = wm * 64 + tm * 16 + (lane & 15);
                int c   = c0 + ((lane >> 4) << 3);
                ldm4(a[tm], sb + SA + row * 512 + ((((c >> 3) ^ (row & 7))) << 4));
            }
            uint32_t bf[2][4];
            #pragma unroll
            for (int tp = 0; tp < 2; ++tp) {
                int j = wn * 32 + tp * 16 + ((lane >> 4) << 3) + (lane & 7);
                int c = c0 + ((lane >> 3) & 1) * 8;
                ldm4(bf[tp], sB + j * 512 + ((((c >> 3) ^ (j & 7))) << 4));
            }
            #pragma unroll
            for (int tm = 0; tm < 4; ++tm)
                #pragma unroll
                for (int tn = 0; tn < 4; ++tn)
                    mma16816(acc[tm][tn], a[tm], &bf[tn >> 1][(tn & 1) * 2]);
        }

        // epilogue: d = (An - 2m) + Bk, margin-tracked argmin
        const int kw = i * 128 + wn * 32;
        #pragma unroll
        for (int tm = 0; tm < 4; ++tm)
            #pragma unroll
            for (int half = 0; half < 2; ++half) {
                const int s = tm * 2 + half;
                const float An = An_r[s];
                #pragma unroll
                for (int tn = 0; tn < 4; ++tn)
                    #pragma unroll
                    for (int col = 0; col < 2; ++col) {
                        int k = kw + tn * 8 + pairc + col;
                        float m = acc[tm][tn][half * 2 + col];
                        float d = __fadd_rn(__fadd_rn(An, -2.0f * m), bsn[k]);
                        if (d < best[s] + MARGIN) {
                            if (d < best[s]) {
                                int inb = best[s] < d + MARGIN;
                                int inc = cv[s]  < d + MARGIN;
                                if (inb && inc) ovf |= (1 << s);
                                else if (inb) { cv[s] = best[s]; ck[s] = bk[s]; }
                                else if (!inc) { cv[s] = BIGF; ck[s] = 0x7fffffff; }
                                best[s] = d; bk[s] = k;
                            } else {
                                if (cv[s] < BIGF) ovf |= (1 << s);
                                else { cv[s] = d; ck[s] = k; }
                            }
                        }
                    }
            }
        __syncthreads();
    }

    // ---- dump per-thread state (reuse SA region) ----
    float* Rbv = (float*)smem;
    int*   Rbk = (int*)(smem + 8192);
    float* Rcv = (float*)(smem + 16384);
    int*   Rck = (int*)(smem + 24576);
    int*   Rov = (int*)(smem + 32768);
    const int cid = wn * 4 + (lane & 3);
    #pragma unroll
    for (int s = 0; s < 8; ++s) {
        int tm = s >> 1, half = s & 1;
        int m = wm * 64 + tm * 16 + (lane >> 2) + half * 8;
        int o = m * 16 + cid;
        Rbv[o] = best[s]; Rbk[o] = bk[s];
        Rcv[o] = cv[s];   Rck[o] = ck[s];
        Rov[o] = (ovf >> s) & 1;
    }
    __syncthreads();

    // ---- merge per point ----
    if (tid < 128) {
        const int m = tid;
        float gb = BIGF;
        #pragma unroll
        for (int c = 0; c < 16; ++c) {
            float v = Rbv[m * 16 + c];
            if (v < gb) gb = v;
        }
        bool full = false;
        int cnt = 0, cds[16];
        #pragma unroll
        for (int c = 0; c < 16; ++c) {
            int o = m * 16 + c;
            if (Rov[o]) full = true;
            float v = Rbv[o];
            if (v < gb + MARGIN) { if (cnt < 16) cds[cnt] = Rbk[o]; ++cnt; }
            float w = Rcv[o];
            if (w < gb + MARGIN) { if (cnt < 16) cds[cnt] = Rck[o]; ++cnt; }
        }
        if (cnt > 16) full = true;
        int n = n0 + m;
        g_An[n] = sAn[m];
        if (full) g_ccnt[n] = 100000;
        else if (cnt == 1) { g_idx[n] = cds[0]; g_ccnt[n] = 1; }
        else {
            g_ccnt[n] = cnt;
            for (int t = 0; t < cnt; ++t) g_cand[n * 16 + t] = cds[t];
        }
    }
}

// ======================= exact recheck: one warp per point =======================
__global__ void k_recheck(const float* __restrict__ z, const float* __restrict__ cb) {
    int gt = blockIdx.x * blockDim.x + threadIdx.x;
    int n = gt >> 5, lane = gt & 31;
    if (n >= NPTS) return;
    int cnt = g_ccnt[n];
    if (cnt <= 1) return;

    const float* zrow = z + (size_t)(n >> 10) * (CDIM * 1024) + (n & 1023);
    const float A = g_An[n];

    float bd = BIGF;
    int   bkk = 0x7fffffff;

    if (cnt <= 16) {
        if (lane < cnt) {
            int k = g_cand[n * 16 + lane];
            const float4* c4 = (const float4*)(cb + (size_t)k * CDIM);
            float acc = 0.f;
            #pragma unroll 4
            for (int c0 = 0; c0 < 64; ++c0) {
                float4 e = c4[c0];
                acc = fmaf(zrow[(size_t)(c0 * 4 + 0) * 1024], e.x, acc);
                acc = fmaf(zrow[(size_t)(c0 * 4 + 1) * 1024], e.y, acc);
                acc = fmaf(zrow[(size_t)(c0 * 4 + 2) * 1024], e.z, acc);
                acc = fmaf(zrow[(size_t)(c0 * 4 + 3) * 1024], e.w, acc);
            }
            bd = __fadd_rn(__fadd_rn(A, -2.0f * acc), g_cbn[k]);
            bkk = k;
        }
    } else {
        for (int k = lane; k < KCODES; k += 32) {
            const float4* c4 = (const float4*)(cb + (size_t)k * CDIM);
            float acc = 0.f;
            #pragma unroll 4
            for (int c0 = 0; c0 < 64; ++c0) {
                float4 e = c4[c0];
                acc = fmaf(zrow[(size_t)(c0 * 4 + 0) * 1024], e.x, acc);
                acc = fmaf(zrow[(size_t)(c0 * 4 + 1) * 1024], e.y, acc);
                acc = fmaf(zrow[(size_t)(c0 * 4 + 2) * 1024], e.z, acc);
                acc = fmaf(zrow[(size_t)(c0 * 4 + 3) * 1024], e.w, acc);
            }
            float d = __fadd_rn(__fadd_rn(A, -2.0f * acc), g_cbn[k]);
            if (d < bd) { bd = d; bkk = k; }   // ascending k per lane
        }
    }
    // (d, k) lexicographic min across warp
    #pragma unroll
    for (int off = 16; off; off >>= 1) {
        float ov = __shfl_down_sync(0xffffffffu, bd, off);
        int   ok = __shfl_down_sync(0xffffffffu, bkk, off);
        if (ov < bd || (ov == bd && ok < bkk)) { bd = ov; bkk = ok; }
    }
    if (lane == 0) g_idx[n] = bkk;
}

// ======================= histogram =======================
__global__ void k_counts() {
    int n = blockIdx.x * blockDim.x + threadIdx.x;
    if (n < NPTS) atomicAdd(&g_cnt[g_idx[n]], 1);
}

// ======================= z_q_st + loss (float4 gather) =======================
__global__ void k_zq(const float* __restrict__ z, const float* __restrict__ cb,
                     float* __restrict__ out) {
    int t = blockIdx.x * blockDim.x + threadIdx.x;   // 4,194,304 threads
    int hw = t & 1023, cg = (t >> 10) & 63, b = t >> 16;
    int n = (b << 10) | hw;
    int idx = g_idx[n];
    float4 e = ((const float4*)cb)[(size_t)idx * 64 + cg];
    size_t base = ((size_t)(b * 256 + cg * 4)) * 1024 + hw;

    double v = 0.0;
    float ev[4] = {e.x, e.y, e.z, e.w};
    #pragma unroll
    for (int j = 0; j < 4; ++j) {
        float ze = z[base + (size_t)j * 1024];
        float diff = __fsub_rn(ev[j], ze);
        out[base + (size_t)j * 1024] = __fadd_rn(ze, diff);
        v += (double)__fmul_rn(diff, diff);
    }

    #pragma unroll
    for (int off = 16; off; off >>= 1)
        v += __shfl_down_sync(0xffffffffu, v, off);
    __shared__ double ws[8];
    int lane = threadIdx.x & 31, w = threadIdx.x >> 5;
    if (lane == 0) ws[w] = v;
    __syncthreads();
    if (w == 0) {
        double s = (lane < 8) ? ws[lane] : 0.0;
        #pragma unroll
        for (int off = 4; off; off >>= 1)
            s += __shfl_down_sync(0xffffffffu, s, off);
        if (lane == 0) atomicAdd(&g_loss, s);
    }
}

// ======================= one-hot encodings =======================
__global__ void k_enc(float* __restrict__ out) {
    int gid = blockIdx.x * blockDim.x + threadIdx.x;  // 67,108,864 float2
    int n  = gid >> 10;
    int k0 = (gid & 1023) << 1;
    int best = g_idx[n];
    float2 v;
    v.x = (k0     == best) ? 1.f : 0.f;
    v.y = (k0 + 1 == best) ? 1.f : 0.f;
    *(float2*)(out + OFF_ENC + (size_t)gid * 2) = v;
}

// ======================= scalars =======================
__global__ void k_scalars(float* __restrict__ out) {
    __shared__ double ssum[256];
    int t = threadIdx.x;
    double s = 0.0;
    for (int k = t; k < KCODES; k += 256) {
        float em = (float)g_cnt[k] * (1.0f / 65536.0f);
        float lg = logf(__fadd_rn(em, 1e-10f));
        s += (double)__fmul_rn(em, lg);
    }
    ssum[t] = s;
    __syncthreads();
    for (int off = 128; off; off >>= 1) {
        if (t < off) ssum[t] += ssum[t + off];
        __syncthreads();
    }
    if (t == 0) {
        float S = (float)ssum[0];
        out[OFF_PERP] = expf(-S);
        double m = g_loss / 16777216.0;
        float mf = (float)m;
        out[OFF_LOSS] = __fadd_rn(mf, __fmul_rn(0.25f, mf));
    }
}

extern "C" void kernel_launch(void* const* d_in, const int* in_sizes, int n_in,
                              void* d_out, int out_size) {
    (void)out_size;
    const float* z  = (const float*)d_in[0];
    const float* cb = (const float*)d_in[1];
    if (n_in >= 2 && in_sizes[0] == KCODES * CDIM) {
        const float* t = z; z = cb; cb = t;
    }
    float* out = (float*)d_out;

    cudaFuncSetAttribute(k_argmin_mma, cudaFuncAttributeMaxDynamicSharedMemorySize, SMTOT);

    k_prep      <<<(KCODES + 255) / 256, 256>>>(cb);
    k_argmin_mma<<<NPTS / 128, TH, SMTOT>>>(z, cb);
    k_recheck   <<<(NPTS * 32) / 256, 256>>>(z, cb);
    k_counts    <<<NPTS / 256, 256>>>();
    k_zq        <<<4194304 / 256, 256>>>(z, cb, out);
    k_enc       <<<67108864 / 256, 256>>>(out);
    k_scalars   <<<1, 256>>>(out);
}

// round 7
// speedup vs baseline: 7.3734x; 7.3734x over previous
#include <cuda_runtime.h>
#include <cuda_bf16.h>
#include <math.h>
#include <stdint.h>

#define NPTS   65536
#define CDIM   256
#define KCODES 2048

#define TH     256
#define NCH    16          // 2048 / 128
#define MARGIN 5e-4f
#define BIGF   3.4e38f

// ---- dynamic smem layout (bytes) ----
#define SA    0            // A tile: 128 rows x 512B (bf16, swizzled)
#define SB0   65536
#define SB1   131072
#define SBS   196608       // norms: 2048 f32
#define SAN   204800       // An: 128 f32
#define SMTOT 205312

// ---- device scratch ----
__device__ int      g_idx[NPTS];
__device__ float    g_cbn[KCODES];
__device__ uint32_t g_cbb[KCODES * 128];   // bf16x2-packed codebook
__device__ float    g_An[NPTS];
__device__ int      g_ccnt[NPTS];
__device__ int      g_cand[NPTS * 16];
__device__ int      g_cnt[KCODES];
__device__ double   g_loss;

// out layout (fp32): [z_q_st 16,777,216 | loss | perplexity | encodings]
#define OFF_LOSS 16777216
#define OFF_PERP 16777217
#define OFF_ENC  16777218

// ======================= helpers =======================
__device__ __forceinline__ uint32_t smem_u32(const void* p) {
    uint32_t a;
    asm("{ .reg .u64 t; cvta.to.shared.u64 t, %1; cvt.u32.u64 %0, t; }" : "=r"(a) : "l"(p));
    return a;
}
__device__ __forceinline__ uint32_t pack2(float a, float b) {
    __nv_bfloat162 t = __floats2bfloat162_rn(a, b);
    return *(uint32_t*)&t;
}
__device__ __forceinline__ void ldm4(uint32_t* r, uint32_t addr) {
    asm volatile("ldmatrix.sync.aligned.m8n8.x4.shared.b16 {%0,%1,%2,%3}, [%4];"
        : "=r"(r[0]), "=r"(r[1]), "=r"(r[2]), "=r"(r[3]) : "r"(addr));
}
__device__ __forceinline__ void mma16816(float* c, const uint32_t* a, const uint32_t* b) {
    asm volatile("mma.sync.aligned.m16n8k16.row.col.f32.bf16.bf16.f32 "
        "{%0,%1,%2,%3}, {%4,%5,%6,%7}, {%8,%9}, {%0,%1,%2,%3};"
        : "+f"(c[0]), "+f"(c[1]), "+f"(c[2]), "+f"(c[3])
        : "r"(a[0]), "r"(a[1]), "r"(a[2]), "r"(a[3]), "r"(b[0]), "r"(b[1]));
}

// ======================= prep: norms + bf16 codebook =======================
__global__ void k_prep(const float* __restrict__ cb) {
    int k = blockIdx.x * blockDim.x + threadIdx.x;
    if (k < KCODES) {
        const float* row = cb + (size_t)k * CDIM;
        float s = 0.f;
        #pragma unroll 8
        for (int c = 0; c < CDIM; ++c) {
            float t = row[c];
            s = __fadd_rn(s, __fmul_rn(t, t));
        }
        g_cbn[k] = s;
        g_cnt[k] = 0;
        #pragma unroll 4
        for (int p = 0; p < 128; ++p)
            g_cbb[(size_t)k * 128 + p] = pack2(row[2 * p], row[2 * p + 1]);
    }
    if (k == 0) g_loss = 0.0;
}

// ======================= HMMA distance GEMM + streaming argmin =======================
__global__ __launch_bounds__(TH, 1)
void k_argmin_mma(const float* __restrict__ z, const float* __restrict__ cb) {
    extern __shared__ char smem[];
    const uint32_t sb = smem_u32(smem);
    const int tid  = threadIdx.x;
    const int lane = tid & 31;
    const int wid  = tid >> 5;
    const int wm   = wid & 1;          // warp row (64 pts)
    const int wn   = wid >> 1;         // warp col (32 codes)

    const int blk = blockIdx.x;        // 0..511
    const int b   = blk >> 3;
    const int hw0 = (blk & 7) << 7;
    const int n0  = blk * 128;
    const float* zb = z + (size_t)b * (CDIM * 1024) + hw0;

    float* bsn = (float*)(smem + SBS);
    float* sAn = (float*)(smem + SAN);

    // ---- stage A (bf16 of z), swizzled [m][c] ----
    for (int it = 0; it < 64; ++it) {
        int e = tid + it * TH;          // 0..16383
        int m = e & 127, c = (e >> 7) << 1;
        float v0 = zb[(size_t)c * 1024 + m];
        float v1 = zb[(size_t)(c + 1) * 1024 + m];
        uint32_t off = (uint32_t)(m * 512 + ((((c >> 3) ^ (m & 7))) << 4) + (c & 7) * 2);
        *(uint32_t*)(smem + SA + off) = pack2(v0, v1);
    }
    // ---- norms to smem ----
    for (int j = tid; j < KCODES; j += TH) bsn[j] = g_cbn[j];

    // ---- An exact (reference rounding) ----
    if (tid < 128) {
        float p[32];
        #pragma unroll
        for (int l = 0; l < 32; ++l) p[l] = 0.f;
        #pragma unroll
        for (int i = 0; i < 8; ++i)
            #pragma unroll
            for (int l = 0; l < 32; ++l) {
                float t = zb[(size_t)(l + 32 * i) * 1024 + tid];
                p[l] = __fadd_rn(p[l], __fmul_rn(t, t));
            }
        #pragma unroll
        for (int off = 16; off >= 1; off >>= 1)
            #pragma unroll
            for (int l = 0; l < 16; ++l)
                if (l < off) p[l] = __fadd_rn(p[l], p[l + off]);
        sAn[tid] = p[0];
    }

    // ---- stage B chunk 0 ----
    for (int it = 0; it < 16; ++it) {
        int e = tid + it * TH;          // 0..4095
        int j = e >> 5, c8 = e & 31;
        uint4 v = *(const uint4*)&g_cbb[(size_t)j * 128 + c8 * 4];
        *(uint4*)(smem + SB0 + j * 512 + ((c8 ^ (j & 7)) << 4)) = v;
    }
    __syncthreads();

    // per-slot argmin state: slot s = tm*2 + half  (8 m-rows per thread)
    float best[8], cv[8];
    int   bk[8], ck[8];
    int   ovf = 0;
    float An_r[8];
    #pragma unroll
    for (int s = 0; s < 8; ++s) {
        best[s] = BIGF; cv[s] = BIGF; bk[s] = 0x7fffffff; ck[s] = 0x7fffffff;
        int tm = s >> 1, half = s & 1;
        An_r[s] = sAn[wm * 64 + tm * 16 + (lane >> 2) + half * 8];
    }

    const int pairc = (lane & 3) * 2;

    for (int i = 0; i < NCH; ++i) {
        const uint32_t sB = sb + ((i & 1) ? SB1 : SB0);

        // prefetch next chunk into the other buffer
        if (i + 1 < NCH) {
            const uint32_t dstb = ((i + 1) & 1) ? SB1 : SB0;   // byte offset into smem[]
            const int kb2 = (i + 1) * 128;
            #pragma unroll
            for (int it = 0; it < 16; ++it) {
                int e = tid + it * TH;
                int j = e >> 5, c8 = e & 31;
                uint4 v = *(const uint4*)&g_cbb[(size_t)(kb2 + j) * 128 + c8 * 4];
                *(uint4*)(smem + dstb + j * 512 + ((c8 ^ (j & 7)) << 4)) = v;
            }
        }

        float acc[4][4][4];
        #pragma unroll
        for (int tm = 0; tm < 4; ++tm)
            #pragma unroll
            for (int tn = 0; tn < 4; ++tn)
                #pragma unroll
                for (int r = 0; r < 4; ++r) acc[tm][tn][r] = 0.f;

        #pragma unroll
        for (int ks = 0; ks < 16; ++ks) {
            const int c0 = ks * 16;
            uint32_t a[4][4];
            #pragma unroll
            for (int tm = 0; tm < 4; ++tm) {
                int row = wm * 64 + tm * 16 + (lane & 15);
                int c   = c0 + ((lane >> 4) << 3);
                ldm4(a[tm], sb + SA + row * 512 + ((((c >> 3) ^ (row & 7))) << 4));
            }
            uint32_t bf[2][4];
            #pragma unroll
            for (int tp = 0; tp < 2; ++tp) {
                int j = wn * 32 + tp * 16 + ((lane >> 4) << 3) + (lane & 7);
                int c = c0 + ((lane >> 3) & 1) * 8;
                ldm4(bf[tp], sB + j * 512 + ((((c >> 3) ^ (j & 7))) << 4));
            }
            #pragma unroll
            for (int tm = 0; tm < 4; ++tm)
                #pragma unroll
                for (int tn = 0; tn < 4; ++tn)
                    mma16816(acc[tm][tn], a[tm], &bf[tn >> 1][(tn & 1) * 2]);
        }

        // epilogue: d = (An - 2m) + Bk, margin-tracked argmin
        const int kw = i * 128 + wn * 32;
        #pragma unroll
        for (int tm = 0; tm < 4; ++tm)
            #pragma unroll
            for (int half = 0; half < 2; ++half) {
                const int s = tm * 2 + half;
                const float An = An_r[s];
                #pragma unroll
                for (int tn = 0; tn < 4; ++tn)
                    #pragma unroll
                    for (int col = 0; col < 2; ++col) {
                        int k = kw + tn * 8 + pairc + col;
                        float m = acc[tm][tn][half * 2 + col];
                        float d = __fadd_rn(__fadd_rn(An, -2.0f * m), bsn[k]);
                        if (d < best[s] + MARGIN) {
                            if (d < best[s]) {
                                int inb = best[s] < d + MARGIN;
                                int inc = cv[s]  < d + MARGIN;
                                if (inb && inc) ovf |= (1 << s);
                                else if (inb) { cv[s] = best[s]; ck[s] = bk[s]; }
                                else if (!inc) { cv[s] = BIGF; ck[s] = 0x7fffffff; }
                                best[s] = d; bk[s] = k;
                            } else {
                                if (cv[s] < BIGF) ovf |= (1 << s);
                                else { cv[s] = d; ck[s] = k; }
                            }
                        }
                    }
            }
        __syncthreads();
    }

    // ---- dump per-thread state (reuse SA region) ----
    float* Rbv = (float*)smem;
    int*   Rbk = (int*)(smem + 8192);
    float* Rcv = (float*)(smem + 16384);
    int*   Rck = (int*)(smem + 24576);
    int*   Rov = (int*)(smem + 32768);
    const int cid = wn * 4 + (lane & 3);
    #pragma unroll
    for (int s = 0; s < 8; ++s) {
        int tm = s >> 1, half = s & 1;
        int m = wm * 64 + tm * 16 + (lane >> 2) + half * 8;
        int o = m * 16 + cid;
        Rbv[o] = best[s]; Rbk[o] = bk[s];
        Rcv[o] = cv[s];   Rck[o] = ck[s];
        Rov[o] = (ovf >> s) & 1;
    }
    __syncthreads();

    // ---- merge per point ----
    if (tid < 128) {
        const int m = tid;
        float gb = BIGF;
        #pragma unroll
        for (int c = 0; c < 16; ++c) {
            float v = Rbv[m * 16 + c];
            if (v < gb) gb = v;
        }
        bool full = false;
        int cnt = 0, cds[16];
        #pragma unroll
        for (int c = 0; c < 16; ++c) {
            int o = m * 16 + c;
            float v = Rbv[o];
            // overflow only matters if the lost values (all >= this slot's final
            // best) could lie within MARGIN of the global best
            if (Rov[o] && v < gb + MARGIN) full = true;
            if (v < gb + MARGIN) { if (cnt < 16) cds[cnt] = Rbk[o]; ++cnt; }
            float w = Rcv[o];
            if (w < gb + MARGIN) { if (cnt < 16) cds[cnt] = Rck[o]; ++cnt; }
        }
        if (cnt > 16) full = true;
        int n = n0 + m;
        g_An[n] = sAn[m];
        if (full) g_ccnt[n] = 100000;
        else if (cnt == 1) { g_idx[n] = cds[0]; g_ccnt[n] = 1; }
        else {
            g_ccnt[n] = cnt;
            for (int t = 0; t < cnt; ++t) g_cand[n * 16 + t] = cds[t];
        }
    }
}

// ======================= exact recheck: one warp per point =======================
__global__ void k_recheck(const float* __restrict__ z, const float* __restrict__ cb) {
    int gt = blockIdx.x * blockDim.x + threadIdx.x;
    int n = gt >> 5, lane = gt & 31;
    if (n >= NPTS) return;
    int cnt = g_ccnt[n];
    if (cnt <= 1) return;

    const float* zrow = z + (size_t)(n >> 10) * (CDIM * 1024) + (n & 1023);
    const float A = g_An[n];

    float bd = BIGF;
    int   bkk = 0x7fffffff;

    if (cnt <= 16) {
        if (lane < cnt) {
            int k = g_cand[n * 16 + lane];
            const float4* c4 = (const float4*)(cb + (size_t)k * CDIM);
            float acc = 0.f;
            #pragma unroll 4
            for (int c0 = 0; c0 < 64; ++c0) {
                float4 e = c4[c0];
                acc = fmaf(zrow[(size_t)(c0 * 4 + 0) * 1024], e.x, acc);
                acc = fmaf(zrow[(size_t)(c0 * 4 + 1) * 1024], e.y, acc);
                acc = fmaf(zrow[(size_t)(c0 * 4 + 2) * 1024], e.z, acc);
                acc = fmaf(zrow[(size_t)(c0 * 4 + 3) * 1024], e.w, acc);
            }
            bd = __fadd_rn(__fadd_rn(A, -2.0f * acc), g_cbn[k]);
            bkk = k;
        }
    } else {
        for (int k = lane; k < KCODES; k += 32) {
            const float4* c4 = (const float4*)(cb + (size_t)k * CDIM);
            float acc = 0.f;
            #pragma unroll 4
            for (int c0 = 0; c0 < 64; ++c0) {
                float4 e = c4[c0];
                acc = fmaf(zrow[(size_t)(c0 * 4 + 0) * 1024], e.x, acc);
                acc = fmaf(zrow[(size_t)(c0 * 4 + 1) * 1024], e.y, acc);
                acc = fmaf(zrow[(size_t)(c0 * 4 + 2) * 1024], e.z, acc);
                acc = fmaf(zrow[(size_t)(c0 * 4 + 3) * 1024], e.w, acc);
            }
            float d = __fadd_rn(__fadd_rn(A, -2.0f * acc), g_cbn[k]);
            if (d < bd) { bd = d; bkk = k; }   // ascending k per lane
        }
    }
    // (d, k) lexicographic min across warp
    #pragma unroll
    for (int off = 16; off; off >>= 1) {
        float ov = __shfl_down_sync(0xffffffffu, bd, off);
        int   ok = __shfl_down_sync(0xffffffffu, bkk, off);
        if (ov < bd || (ov == bd && ok < bkk)) { bd = ov; bkk = ok; }
    }
    if (lane == 0) g_idx[n] = bkk;
}

// ======================= histogram =======================
__global__ void k_counts() {
    int n = blockIdx.x * blockDim.x + threadIdx.x;
    if (n < NPTS) atomicAdd(&g_cnt[g_idx[n]], 1);
}

// ======================= z_q_st + loss (float4 gather) =======================
__global__ void k_zq(const float* __restrict__ z, const float* __restrict__ cb,
                     float* __restrict__ out) {
    int t = blockIdx.x * blockDim.x + threadIdx.x;   // 4,194,304 threads
    int hw = t & 1023, cg = (t >> 10) & 63, b = t >> 16;
    int n = (b << 10) | hw;
    int idx = g_idx[n];
    float4 e = ((const float4*)cb)[(size_t)idx * 64 + cg];
    size_t base = ((size_t)(b * 256 + cg * 4)) * 1024 + hw;

    double v = 0.0;
    float ev[4] = {e.x, e.y, e.z, e.w};
    #pragma unroll
    for (int j = 0; j < 4; ++j) {
        float ze = z[base + (size_t)j * 1024];
        float diff = __fsub_rn(ev[j], ze);
        out[base + (size_t)j * 1024] = __fadd_rn(ze, diff);
        v += (double)__fmul_rn(diff, diff);
    }

    #pragma unroll
    for (int off = 16; off; off >>= 1)
        v += __shfl_down_sync(0xffffffffu, v, off);
    __shared__ double ws[8];
    int lane = threadIdx.x & 31, w = threadIdx.x >> 5;
    if (lane == 0) ws[w] = v;
    __syncthreads();
    if (w == 0) {
        double s = (lane < 8) ? ws[lane] : 0.0;
        #pragma unroll
        for (int off = 4; off; off >>= 1)
            s += __shfl_down_sync(0xffffffffu, s, off);
        if (lane == 0) atomicAdd(&g_loss, s);
    }
}

// ======================= one-hot encodings =======================
__global__ void k_enc(float* __restrict__ out) {
    int gid = blockIdx.x * blockDim.x + threadIdx.x;  // 67,108,864 float2
    int n  = gid >> 10;
    int k0 = (gid & 1023) << 1;
    int best = g_idx[n];
    float2 v;
    v.x = (k0     == best) ? 1.f : 0.f;
    v.y = (k0 + 1 == best) ? 1.f : 0.f;
    *(float2*)(out + OFF_ENC + (size_t)gid * 2) = v;
}

// ======================= scalars =======================
__global__ void k_scalars(float* __restrict__ out) {
    __shared__ double ssum[256];
    int t = threadIdx.x;
    double s = 0.0;
    for (int k = t; k < KCODES; k += 256) {
        float em = (float)g_cnt[k] * (1.0f / 65536.0f);
        float lg = logf(__fadd_rn(em, 1e-10f));
        s += (double)__fmul_rn(em, lg);
    }
    ssum[t] = s;
    __syncthreads();
    for (int off = 128; off; off >>= 1) {
        if (t < off) ssum[t] += ssum[t + off];
        __syncthreads();
    }
    if (t == 0) {
        float S = (float)ssum[0];
        out[OFF_PERP] = expf(-S);
        double m = g_loss / 16777216.0;
        float mf = (float)m;
        out[OFF_LOSS] = __fadd_rn(mf, __fmul_rn(0.25f, mf));
    }
}

extern "C" void kernel_launch(void* const* d_in, const int* in_sizes, int n_in,
                              void* d_out, int out_size) {
    (void)out_size;
    const float* z  = (const float*)d_in[0];
    const float* cb = (const float*)d_in[1];
    if (n_in >= 2 && in_sizes[0] == KCODES * CDIM) {
        const float* t = z; z = cb; cb = t;
    }
    float* out = (float*)d_out;

    cudaFuncSetAttribute(k_argmin_mma, cudaFuncAttributeMaxDynamicSharedMemorySize, SMTOT);

    k_prep      <<<(KCODES + 255) / 256, 256>>>(cb);
    k_argmin_mma<<<NPTS / 128, TH, SMTOT>>>(z, cb);
    k_recheck   <<<(NPTS * 32) / 256, 256>>>(z, cb);
    k_counts    <<<NPTS / 256, 256>>>();
    k_zq        <<<4194304 / 256, 256>>>(z, cb, out);
    k_enc       <<<67108864 / 256, 256>>>(out);
    k_scalars   <<<1, 256>>>(out);
}

// round 8
// speedup vs baseline: 16.0089x; 2.1712x over previous
#include <cuda_runtime.h>
#include <cuda_bf16.h>
#include <math.h>
#include <stdint.h>

#define NPTS   65536
#define CDIM   256
#define KCODES 2048

#define TH     256
#define NCH    16          // 2048 / 128
#define MARGIN 2.5e-4f
#define BIGF   3.4e38f

// ---- dynamic smem layout (bytes) ----
#define SA    0            // A tile: 128 rows x 512B (bf16, swizzled)
#define SB0   65536
#define SB1   131072
#define SBS   196608       // norms: 2048 f32
#define SAN   204800       // An: 128 f32
#define SMTOT 205312

// ---- device scratch ----
__device__ int      g_idx[NPTS];
__device__ float    g_cbn[KCODES];
__device__ uint32_t g_cbb[KCODES * 128];   // bf16x2-packed codebook
__device__ float    g_An[NPTS];
__device__ int      g_ccnt[NPTS];
__device__ int      g_cand[NPTS * 16];
__device__ int      g_cnt[KCODES];
__device__ double   g_loss;

// out layout (fp32): [z_q_st 16,777,216 | loss | perplexity | encodings]
#define OFF_LOSS 16777216
#define OFF_PERP 16777217
#define OFF_ENC  16777218

// ======================= helpers =======================
__device__ __forceinline__ uint32_t smem_u32(const void* p) {
    uint32_t a;
    asm("{ .reg .u64 t; cvta.to.shared.u64 t, %1; cvt.u32.u64 %0, t; }" : "=r"(a) : "l"(p));
    return a;
}
__device__ __forceinline__ uint32_t pack2(float a, float b) {
    __nv_bfloat162 t = __floats2bfloat162_rn(a, b);
    return *(uint32_t*)&t;
}
__device__ __forceinline__ void ldm4(uint32_t* r, uint32_t addr) {
    asm volatile("ldmatrix.sync.aligned.m8n8.x4.shared.b16 {%0,%1,%2,%3}, [%4];"
        : "=r"(r[0]), "=r"(r[1]), "=r"(r[2]), "=r"(r[3]) : "r"(addr));
}
__device__ __forceinline__ void mma16816(float* c, const uint32_t* a, const uint32_t* b) {
    asm volatile("mma.sync.aligned.m16n8k16.row.col.f32.bf16.bf16.f32 "
        "{%0,%1,%2,%3}, {%4,%5,%6,%7}, {%8,%9}, {%0,%1,%2,%3};"
        : "+f"(c[0]), "+f"(c[1]), "+f"(c[2]), "+f"(c[3])
        : "r"(a[0]), "r"(a[1]), "r"(a[2]), "r"(a[3]), "r"(b[0]), "r"(b[1]));
}

// ======================= prep: norms + bf16 codebook =======================
__global__ void k_prep(const float* __restrict__ cb) {
    int k = blockIdx.x * blockDim.x + threadIdx.x;
    if (k < KCODES) {
        const float* row = cb + (size_t)k * CDIM;
        float s = 0.f;
        #pragma unroll 8
        for (int c = 0; c < CDIM; ++c) {
            float t = row[c];
            s = __fadd_rn(s, __fmul_rn(t, t));
        }
        g_cbn[k] = s;
        g_cnt[k] = 0;
        #pragma unroll 4
        for (int p = 0; p < 128; ++p)
            g_cbb[(size_t)k * 128 + p] = pack2(row[2 * p], row[2 * p + 1]);
    }
    if (k == 0) g_loss = 0.0;
}

// no-op spacers so k_argmin_mma is the 4th launch (ncu captures launch #4)
__global__ void k_nop() {}

// ======================= HMMA distance GEMM + streaming argmin =======================
__global__ __launch_bounds__(TH, 1)
void k_argmin_mma(const float* __restrict__ z, const float* __restrict__ cb) {
    extern __shared__ char smem[];
    const uint32_t sb = smem_u32(smem);
    const int tid  = threadIdx.x;
    const int lane = tid & 31;
    const int wid  = tid >> 5;
    const int wm   = wid & 1;          // warp row (64 pts)
    const int wn   = wid >> 1;         // warp col (32 codes)

    const int blk = blockIdx.x;        // 0..511
    const int b   = blk >> 3;
    const int hw0 = (blk & 7) << 7;
    const int n0  = blk * 128;
    const float* zb = z + (size_t)b * (CDIM * 1024) + hw0;

    float* bsn = (float*)(smem + SBS);
    float* sAn = (float*)(smem + SAN);

    // ---- stage A (bf16 of z), swizzled [m][c] ----
    for (int it = 0; it < 64; ++it) {
        int e = tid + it * TH;          // 0..16383
        int m = e & 127, c = (e >> 7) << 1;
        float v0 = zb[(size_t)c * 1024 + m];
        float v1 = zb[(size_t)(c + 1) * 1024 + m];
        uint32_t off = (uint32_t)(m * 512 + ((((c >> 3) ^ (m & 7))) << 4) + (c & 7) * 2);
        *(uint32_t*)(smem + SA + off) = pack2(v0, v1);
    }
    // ---- norms to smem ----
    for (int j = tid; j < KCODES; j += TH) bsn[j] = g_cbn[j];

    // ---- An exact (reference rounding) ----
    if (tid < 128) {
        float p[32];
        #pragma unroll
        for (int l = 0; l < 32; ++l) p[l] = 0.f;
        #pragma unroll
        for (int i = 0; i < 8; ++i)
            #pragma unroll
            for (int l = 0; l < 32; ++l) {
                float t = zb[(size_t)(l + 32 * i) * 1024 + tid];
                p[l] = __fadd_rn(p[l], __fmul_rn(t, t));
            }
        #pragma unroll
        for (int off = 16; off >= 1; off >>= 1)
            #pragma unroll
            for (int l = 0; l < 16; ++l)
                if (l < off) p[l] = __fadd_rn(p[l], p[l + off]);
        sAn[tid] = p[0];
    }

    // ---- stage B chunk 0 ----
    for (int it = 0; it < 16; ++it) {
        int e = tid + it * TH;          // 0..4095
        int j = e >> 5, c8 = e & 31;
        uint4 v = *(const uint4*)&g_cbb[(size_t)j * 128 + c8 * 4];
        *(uint4*)(smem + SB0 + j * 512 + ((c8 ^ (j & 7)) << 4)) = v;
    }
    __syncthreads();

    // per-slot argmin state: slot s = tm*2 + half  (8 m-rows per thread)
    // best/bk: running min; cv/ck: one extra in-window candidate;
    // ovfv: min of all candidate values LOST from the window (exact).
    float best[8], cv[8], ovfv[8];
    int   bk[8], ck[8];
    float An_r[8];
    #pragma unroll
    for (int s = 0; s < 8; ++s) {
        best[s] = BIGF; cv[s] = BIGF; ovfv[s] = BIGF;
        bk[s] = 0x7fffffff; ck[s] = 0x7fffffff;
        int tm = s >> 1, half = s & 1;
        An_r[s] = sAn[wm * 64 + tm * 16 + (lane >> 2) + half * 8];
    }

    const int pairc = (lane & 3) * 2;

    for (int i = 0; i < NCH; ++i) {
        const uint32_t sB = sb + ((i & 1) ? SB1 : SB0);

        // prefetch next chunk into the other buffer
        if (i + 1 < NCH) {
            const uint32_t dstb = ((i + 1) & 1) ? SB1 : SB0;   // byte offset
            const int kb2 = (i + 1) * 128;
            #pragma unroll
            for (int it = 0; it < 16; ++it) {
                int e = tid + it * TH;
                int j = e >> 5, c8 = e & 31;
                uint4 v = *(const uint4*)&g_cbb[(size_t)(kb2 + j) * 128 + c8 * 4];
                *(uint4*)(smem + dstb + j * 512 + ((c8 ^ (j & 7)) << 4)) = v;
            }
        }

        float acc[4][4][4];
        #pragma unroll
        for (int tm = 0; tm < 4; ++tm)
            #pragma unroll
            for (int tn = 0; tn < 4; ++tn)
                #pragma unroll
                for (int r = 0; r < 4; ++r) acc[tm][tn][r] = 0.f;

        #pragma unroll
        for (int ks = 0; ks < 16; ++ks) {
            const int c0 = ks * 16;
            uint32_t a[4][4];
            #pragma unroll
            for (int tm = 0; tm < 4; ++tm) {
                int row = wm * 64 + tm * 16 + (lane & 15);
                int c   = c0 + ((lane >> 4) << 3);
                ldm4(a[tm], sb + SA + row * 512 + ((((c >> 3) ^ (row & 7))) << 4));
            }
            uint32_t bf[2][4];
            #pragma unroll
            for (int tp = 0; tp < 2; ++tp) {
                int j = wn * 32 + tp * 16 + ((lane >> 4) << 3) + (lane & 7);
                int c = c0 + ((lane >> 3) & 1) * 8;
                ldm4(bf[tp], sB + j * 512 + ((((c >> 3) ^ (j & 7))) << 4));
            }
            #pragma unroll
            for (int tm = 0; tm < 4; ++tm)
                #pragma unroll
                for (int tn = 0; tn < 4; ++tn)
                    mma16816(acc[tm][tn], a[tm], &bf[tn >> 1][(tn & 1) * 2]);
        }

        // epilogue: d = (An - 2m) + Bk, margin-tracked argmin with exact loss record
        const int kw = i * 128 + wn * 32;
        #pragma unroll
        for (int tm = 0; tm < 4; ++tm)
            #pragma unroll
            for (int half = 0; half < 2; ++half) {
                const int s = tm * 2 + half;
                const float An = An_r[s];
                #pragma unroll
                for (int tn = 0; tn < 4; ++tn)
                    #pragma unroll
                    for (int col = 0; col < 2; ++col) {
                        int k = kw + tn * 8 + pairc + col;
                        float m = acc[tm][tn][half * 2 + col];
                        float d = __fadd_rn(__fadd_rn(An, -2.0f * m), bsn[k]);
                        if (d < best[s] + MARGIN) {
                            if (d < best[s]) {
                                float ob = best[s]; int obk = bk[s];
                                best[s] = d; bk[s] = k;
                                if (ob < d + MARGIN) {
                                    if (cv[s] < d + MARGIN) {
                                        // both in new window: keep smaller as cv, record lost
                                        if (ob < cv[s]) { ovfv[s] = fminf(ovfv[s], cv[s]); cv[s] = ob; ck[s] = obk; }
                                        else            { ovfv[s] = fminf(ovfv[s], ob); }
                                    } else { cv[s] = ob; ck[s] = obk; }
                                } else {
                                    if (cv[s] >= d + MARGIN) { cv[s] = BIGF; ck[s] = 0x7fffffff; }
                                }
                            } else {
                                if (d < cv[s]) {
                                    if (cv[s] < BIGF) ovfv[s] = fminf(ovfv[s], cv[s]);
                                    cv[s] = d; ck[s] = k;
                                } else {
                                    ovfv[s] = fminf(ovfv[s], d);
                                }
                            }
                        }
                    }
            }
        __syncthreads();
    }

    // ---- dump per-thread state (reuse SA region) ----
    float* Rbv = (float*)smem;
    int*   Rbk = (int*)(smem + 8192);
    float* Rcv = (float*)(smem + 16384);
    int*   Rck = (int*)(smem + 24576);
    float* Rof = (float*)(smem + 32768);
    const int cid = wn * 4 + (lane & 3);
    #pragma unroll
    for (int s = 0; s < 8; ++s) {
        int tm = s >> 1, half = s & 1;
        int m = wm * 64 + tm * 16 + (lane >> 2) + half * 8;
        int o = m * 16 + cid;
        Rbv[o] = best[s]; Rbk[o] = bk[s];
        Rcv[o] = cv[s];   Rck[o] = ck[s];
        Rof[o] = ovfv[s];
    }
    __syncthreads();

    // ---- merge per point ----
    if (tid < 128) {
        const int m = tid;
        float gb = BIGF;
        #pragma unroll
        for (int c = 0; c < 16; ++c) {
            float v = Rbv[m * 16 + c];
            if (v < gb) gb = v;
        }
        bool full = false;
        int cnt = 0, cds[16];
        #pragma unroll
        for (int c = 0; c < 16; ++c) {
            int o = m * 16 + c;
            // a lost value below gb+MARGIN means unknown candidates exist
            if (Rof[o] < gb + MARGIN) full = true;
            float v = Rbv[o];
            if (v < gb + MARGIN) { if (cnt < 16) cds[cnt] = Rbk[o]; ++cnt; }
            float w = Rcv[o];
            if (w < gb + MARGIN) { if (cnt < 16) cds[cnt] = Rck[o]; ++cnt; }
        }
        if (cnt > 16) full = true;
        int n = n0 + m;
        g_An[n] = sAn[m];
        if (full) g_ccnt[n] = 100000;
        else if (cnt == 1) { g_idx[n] = cds[0]; g_ccnt[n] = 1; }
        else {
            g_ccnt[n] = cnt;
            for (int t = 0; t < cnt; ++t) g_cand[n * 16 + t] = cds[t];
        }
    }
}

// ======================= exact recheck: one warp per point =======================
__global__ void k_recheck(const float* __restrict__ z, const float* __restrict__ cb) {
    int gt = blockIdx.x * blockDim.x + threadIdx.x;
    int n = gt >> 5, lane = gt & 31;
    if (n >= NPTS) return;
    int cnt = g_ccnt[n];
    if (cnt <= 1) return;

    const float* zrow = z + (size_t)(n >> 10) * (CDIM * 1024) + (n & 1023);
    const float A = g_An[n];

    float bd = BIGF;
    int   bkk = 0x7fffffff;

    if (cnt <= 16) {
        if (lane < cnt) {
            int k = g_cand[n * 16 + lane];
            const float4* c4 = (const float4*)(cb + (size_t)k * CDIM);
            float acc = 0.f;
            #pragma unroll 4
            for (int c0 = 0; c0 < 64; ++c0) {
                float4 e = c4[c0];
                acc = fmaf(zrow[(size_t)(c0 * 4 + 0) * 1024], e.x, acc);
                acc = fmaf(zrow[(size_t)(c0 * 4 + 1) * 1024], e.y, acc);
                acc = fmaf(zrow[(size_t)(c0 * 4 + 2) * 1024], e.z, acc);
                acc = fmaf(zrow[(size_t)(c0 * 4 + 3) * 1024], e.w, acc);
            }
            bd = __fadd_rn(__fadd_rn(A, -2.0f * acc), g_cbn[k]);
            bkk = k;
        }
    } else {
        for (int k = lane; k < KCODES; k += 32) {
            const float4* c4 = (const float4*)(cb + (size_t)k * CDIM);
            float acc = 0.f;
            #pragma unroll 4
            for (int c0 = 0; c0 < 64; ++c0) {
                float4 e = c4[c0];
                acc = fmaf(zrow[(size_t)(c0 * 4 + 0) * 1024], e.x, acc);
                acc = fmaf(zrow[(size_t)(c0 * 4 + 1) * 1024], e.y, acc);
                acc = fmaf(zrow[(size_t)(c0 * 4 + 2) * 1024], e.z, acc);
                acc = fmaf(zrow[(size_t)(c0 * 4 + 3) * 1024], e.w, acc);
            }
            float d = __fadd_rn(__fadd_rn(A, -2.0f * acc), g_cbn[k]);
            if (d < bd) { bd = d; bkk = k; }   // ascending k per lane
        }
    }
    // (d, k) lexicographic min across warp
    #pragma unroll
    for (int off = 16; off; off >>= 1) {
        float ov = __shfl_down_sync(0xffffffffu, bd, off);
        int   ok = __shfl_down_sync(0xffffffffu, bkk, off);
        if (ov < bd || (ov == bd && ok < bkk)) { bd = ov; bkk = ok; }
    }
    if (lane == 0) g_idx[n] = bkk;
}

// ======================= histogram =======================
__global__ void k_counts() {
    int n = blockIdx.x * blockDim.x + threadIdx.x;
    if (n < NPTS) atomicAdd(&g_cnt[g_idx[n]], 1);
}

// ======================= z_q_st + loss (float4 gather) =======================
__global__ void k_zq(const float* __restrict__ z, const float* __restrict__ cb,
                     float* __restrict__ out) {
    int t = blockIdx.x * blockDim.x + threadIdx.x;   // 4,194,304 threads
    int hw = t & 1023, cg = (t >> 10) & 63, b = t >> 16;
    int n = (b << 10) | hw;
    int idx = g_idx[n];
    float4 e = ((const float4*)cb)[(size_t)idx * 64 + cg];
    size_t base = ((size_t)(b * 256 + cg * 4)) * 1024 + hw;

    double v = 0.0;
    float ev[4] = {e.x, e.y, e.z, e.w};
    #pragma unroll
    for (int j = 0; j < 4; ++j) {
        float ze = z[base + (size_t)j * 1024];
        float diff = __fsub_rn(ev[j], ze);
        out[base + (size_t)j * 1024] = __fadd_rn(ze, diff);
        v += (double)__fmul_rn(diff, diff);
    }

    #pragma unroll
    for (int off = 16; off; off >>= 1)
        v += __shfl_down_sync(0xffffffffu, v, off);
    __shared__ double ws[8];
    int lane = threadIdx.x & 31, w = threadIdx.x >> 5;
    if (lane == 0) ws[w] = v;
    __syncthreads();
    if (w == 0) {
        double s = (lane < 8) ? ws[lane] : 0.0;
        #pragma unroll
        for (int off = 4; off; off >>= 1)
            s += __shfl_down_sync(0xffffffffu, s, off);
        if (lane == 0) atomicAdd(&g_loss, s);
    }
}

// ======================= one-hot encodings =======================
__global__ void k_enc(float* __restrict__ out) {
    int gid = blockIdx.x * blockDim.x + threadIdx.x;  // 67,108,864 float2
    int n  = gid >> 10;
    int k0 = (gid & 1023) << 1;
    int best = g_idx[n];
    float2 v;
    v.x = (k0     == best) ? 1.f : 0.f;
    v.y = (k0 + 1 == best) ? 1.f : 0.f;
    *(float2*)(out + OFF_ENC + (size_t)gid * 2) = v;
}

// ======================= scalars =======================
__global__ void k_scalars(float* __restrict__ out) {
    __shared__ double ssum[256];
    int t = threadIdx.x;
    double s = 0.0;
    for (int k = t; k < KCODES; k += 256) {
        float em = (float)g_cnt[k] * (1.0f / 65536.0f);
        float lg = logf(__fadd_rn(em, 1e-10f));
        s += (double)__fmul_rn(em, lg);
    }
    ssum[t] = s;
    __syncthreads();
    for (int off = 128; off; off >>= 1) {
        if (t < off) ssum[t] += ssum[t + off];
        __syncthreads();
    }
    if (t == 0) {
        float S = (float)ssum[0];
        out[OFF_PERP] = expf(-S);
        double m = g_loss / 16777216.0;
        float mf = (float)m;
        out[OFF_LOSS] = __fadd_rn(mf, __fmul_rn(0.25f, mf));
    }
}

extern "C" void kernel_launch(void* const* d_in, const int* in_sizes, int n_in,
                              void* d_out, int out_size) {
    (void)out_size;
    const float* z  = (const float*)d_in[0];
    const float* cb = (const float*)d_in[1];
    if (n_in >= 2 && in_sizes[0] == KCODES * CDIM) {
        const float* t = z; z = cb; cb = t;
    }
    float* out = (float*)d_out;

    cudaFuncSetAttribute(k_argmin_mma, cudaFuncAttributeMaxDynamicSharedMemorySize, SMTOT);

    k_prep      <<<(KCODES + 255) / 256, 256>>>(cb);
    k_nop       <<<1, 32>>>();
    k_nop       <<<1, 32>>>();
    k_argmin_mma<<<NPTS / 128, TH, SMTOT>>>(z, cb);   // launch #4 -> ncu capture
    k_recheck   <<<(NPTS * 32) / 256, 256>>>(z, cb);
    k_counts    <<<NPTS / 256, 256>>>();
    k_zq        <<<4194304 / 256, 256>>>(z, cb, out);
    k_enc       <<<67108864 / 256, 256>>>(out);
    k_scalars   <<<1, 256>>>(out);
}

// round 9
// speedup vs baseline: 19.8606x; 1.2406x over previous
#include <cuda_runtime.h>
#include <cuda_bf16.h>
#include <math.h>
#include <stdint.h>

#define NPTS   65536
#define CDIM   256
#define KCODES 2048

#define TH     512
#define NCH    16          // 2048 / 128
#define MARGIN 2.5e-4f
#define BIGF   3.4e38f

// ---- dynamic smem layout (bytes) ----
#define SA    0            // A tile: 128 rows x 512B (bf16, swizzled)
#define SB0   65536
#define SB1   131072
#define SBS   196608       // norms: 2048 f32
#define SAN   204800       // An: 128 f32
#define SMTOT 205312

// ---- device scratch ----
__device__ int      g_idx[NPTS];
__device__ float    g_cbn[KCODES];
__device__ uint32_t g_cbb[KCODES * 128];   // bf16x2-packed codebook
__device__ float    g_An[NPTS];
__device__ int      g_ccnt[NPTS];
__device__ int      g_cand[NPTS * 16];
__device__ int      g_cnt[KCODES];
__device__ double   g_loss;

// out layout (fp32): [z_q_st 16,777,216 | loss | perplexity | encodings]
#define OFF_LOSS 16777216
#define OFF_PERP 16777217
#define OFF_ENC  16777218

// ======================= helpers =======================
__device__ __forceinline__ uint32_t smem_u32(const void* p) {
    uint32_t a;
    asm("{ .reg .u64 t; cvta.to.shared.u64 t, %1; cvt.u32.u64 %0, t; }" : "=r"(a) : "l"(p));
    return a;
}
__device__ __forceinline__ uint32_t pack2(float a, float b) {
    __nv_bfloat162 t = __floats2bfloat162_rn(a, b);
    return *(uint32_t*)&t;
}
__device__ __forceinline__ void ldm4(uint32_t* r, uint32_t addr) {
    asm volatile("ldmatrix.sync.aligned.m8n8.x4.shared.b16 {%0,%1,%2,%3}, [%4];"
        : "=r"(r[0]), "=r"(r[1]), "=r"(r[2]), "=r"(r[3]) : "r"(addr));
}
__device__ __forceinline__ void mma16816(float* c, const uint32_t* a, const uint32_t* b) {
    asm volatile("mma.sync.aligned.m16n8k16.row.col.f32.bf16.bf16.f32 "
        "{%0,%1,%2,%3}, {%4,%5,%6,%7}, {%8,%9}, {%0,%1,%2,%3};"
        : "+f"(c[0]), "+f"(c[1]), "+f"(c[2]), "+f"(c[3])
        : "r"(a[0]), "r"(a[1]), "r"(a[2]), "r"(a[3]), "r"(b[0]), "r"(b[1]));
}

// ======================= prep: norms (bit-exact serial order) =======================
__global__ void k_prep(const float* __restrict__ cb) {
    int k = blockIdx.x * blockDim.x + threadIdx.x;
    if (k < KCODES) {
        const float4* row = (const float4*)(cb + (size_t)k * CDIM);
        float s = 0.f;
        #pragma unroll 4
        for (int c4 = 0; c4 < 64; ++c4) {
            float4 v = row[c4];
            s = __fadd_rn(s, __fmul_rn(v.x, v.x));
            s = __fadd_rn(s, __fmul_rn(v.y, v.y));
            s = __fadd_rn(s, __fmul_rn(v.z, v.z));
            s = __fadd_rn(s, __fmul_rn(v.w, v.w));
        }
        g_cbn[k] = s;
        g_cnt[k] = 0;
    }
    if (k == 0) g_loss = 0.0;
}

// coalesced bf16 codebook conversion
__global__ void k_conv(const float* __restrict__ cb) {
    int i = blockIdx.x * blockDim.x + threadIdx.x;   // 262144
    float2 v = ((const float2*)cb)[i];
    g_cbb[i] = pack2(v.x, v.y);
}

// no-op spacer so k_argmin_mma is kernel launch #4 (ncu captures #4)
__global__ void k_nop() {}

// ======================= HMMA distance GEMM + streaming argmin =======================
__global__ __launch_bounds__(TH, 1)
void k_argmin_mma(const float* __restrict__ z, const float* __restrict__ cb) {
    extern __shared__ char smem[];
    const uint32_t sb = smem_u32(smem);
    const int tid  = threadIdx.x;
    const int lane = tid & 31;
    const int wid  = tid >> 5;         // 0..15
    const int wm   = wid >> 2;         // 0..3  (32 pts each)
    const int wn   = wid & 3;          // 0..3  (32 codes each)

    const int blk = blockIdx.x;        // 0..511
    const int b   = blk >> 3;
    const int hw0 = (blk & 7) << 7;
    const int n0  = blk * 128;
    const float* zb = z + (size_t)b * (CDIM * 1024) + hw0;

    float* bsn = (float*)(smem + SBS);
    float* sAn = (float*)(smem + SAN);

    // ---- stage A (bf16 of z), swizzled [m][c] ----
    #pragma unroll 4
    for (int it = 0; it < 32; ++it) {
        int e = tid + it * TH;          // 0..16383
        int m = e & 127, c = (e >> 7) << 1;
        float v0 = zb[(size_t)c * 1024 + m];
        float v1 = zb[(size_t)(c + 1) * 1024 + m];
        uint32_t off = (uint32_t)(m * 512 + ((((c >> 3) ^ (m & 7))) << 4) + (c & 7) * 2);
        *(uint32_t*)(smem + SA + off) = pack2(v0, v1);
    }
    // ---- norms to smem ----
    for (int j = tid; j < KCODES; j += TH) bsn[j] = g_cbn[j];

    // ---- An exact (reference rounding) ----
    if (tid < 128) {
        float p[32];
        #pragma unroll
        for (int l = 0; l < 32; ++l) p[l] = 0.f;
        #pragma unroll
        for (int i = 0; i < 8; ++i)
            #pragma unroll
            for (int l = 0; l < 32; ++l) {
                float t = zb[(size_t)(l + 32 * i) * 1024 + tid];
                p[l] = __fadd_rn(p[l], __fmul_rn(t, t));
            }
        #pragma unroll
        for (int off = 16; off >= 1; off >>= 1)
            #pragma unroll
            for (int l = 0; l < 16; ++l)
                if (l < off) p[l] = __fadd_rn(p[l], p[l + off]);
        sAn[tid] = p[0];
    }

    // ---- stage B chunk 0 ----
    #pragma unroll
    for (int it = 0; it < 8; ++it) {
        int e = tid + it * TH;          // 0..4095
        int j = e >> 5, c8 = e & 31;
        uint4 v = *(const uint4*)&g_cbb[(size_t)j * 128 + c8 * 4];
        *(uint4*)(smem + SB0 + j * 512 + ((c8 ^ (j & 7)) << 4)) = v;
    }
    __syncthreads();

    // per-slot argmin state: slot s = tm*2 + half  (4 m-rows per thread)
    float best[4], cv[4], ovfv[4];
    int   bk[4], ck[4];
    float An_r[4];
    #pragma unroll
    for (int s = 0; s < 4; ++s) {
        best[s] = BIGF; cv[s] = BIGF; ovfv[s] = BIGF;
        bk[s] = 0x7fffffff; ck[s] = 0x7fffffff;
        int tm = s >> 1, half = s & 1;
        An_r[s] = sAn[wm * 32 + tm * 16 + (lane >> 2) + half * 8];
    }

    const int pairc = (lane & 3) * 2;

    for (int i = 0; i < NCH; ++i) {
        const uint32_t sB = sb + ((i & 1) ? SB1 : SB0);

        // prefetch next chunk into the other buffer
        if (i + 1 < NCH) {
            const uint32_t dstb = ((i + 1) & 1) ? SB1 : SB0;   // byte offset
            const int kb2 = (i + 1) * 128;
            #pragma unroll
            for (int it = 0; it < 8; ++it) {
                int e = tid + it * TH;
                int j = e >> 5, c8 = e & 31;
                uint4 v = *(const uint4*)&g_cbb[(size_t)(kb2 + j) * 128 + c8 * 4];
                *(uint4*)(smem + dstb + j * 512 + ((c8 ^ (j & 7)) << 4)) = v;
            }
        }

        float acc[2][4][4];
        #pragma unroll
        for (int tm = 0; tm < 2; ++tm)
            #pragma unroll
            for (int tn = 0; tn < 4; ++tn)
                #pragma unroll
                for (int r = 0; r < 4; ++r) acc[tm][tn][r] = 0.f;

        #pragma unroll
        for (int ks = 0; ks < 16; ++ks) {
            const int c0 = ks * 16;
            uint32_t a[2][4];
            #pragma unroll
            for (int tm = 0; tm < 2; ++tm) {
                int row = wm * 32 + tm * 16 + (lane & 15);
                int c   = c0 + ((lane >> 4) << 3);
                ldm4(a[tm], sb + SA + row * 512 + ((((c >> 3) ^ (row & 7))) << 4));
            }
            uint32_t bf[2][4];
            #pragma unroll
            for (int tp = 0; tp < 2; ++tp) {
                int j = wn * 32 + tp * 16 + ((lane >> 4) << 3) + (lane & 7);
                int c = c0 + ((lane >> 3) & 1) * 8;
                ldm4(bf[tp], sB + j * 512 + ((((c >> 3) ^ (j & 7))) << 4));
            }
            #pragma unroll
            for (int tm = 0; tm < 2; ++tm)
                #pragma unroll
                for (int tn = 0; tn < 4; ++tn)
                    mma16816(acc[tm][tn], a[tm], &bf[tn >> 1][(tn & 1) * 2]);
        }

        // epilogue: d = (An - 2m) + Bk, margin-tracked argmin with exact loss record
        const int kw = i * 128 + wn * 32;
        #pragma unroll
        for (int tm = 0; tm < 2; ++tm)
            #pragma unroll
            for (int half = 0; half < 2; ++half) {
                const int s = tm * 2 + half;
                const float An = An_r[s];
                #pragma unroll
                for (int tn = 0; tn < 4; ++tn)
                    #pragma unroll
                    for (int col = 0; col < 2; ++col) {
                        int k = kw + tn * 8 + pairc + col;
                        float m = acc[tm][tn][half * 2 + col];
                        float d = __fadd_rn(__fadd_rn(An, -2.0f * m), bsn[k]);
                        if (d < best[s] + MARGIN) {
                            if (d < best[s]) {
                                float ob = best[s]; int obk = bk[s];
                                best[s] = d; bk[s] = k;
                                if (ob < d + MARGIN) {
                                    if (cv[s] < d + MARGIN) {
                                        if (ob < cv[s]) { ovfv[s] = fminf(ovfv[s], cv[s]); cv[s] = ob; ck[s] = obk; }
                                        else            { ovfv[s] = fminf(ovfv[s], ob); }
                                    } else { cv[s] = ob; ck[s] = obk; }
                                } else {
                                    if (cv[s] >= d + MARGIN) { cv[s] = BIGF; ck[s] = 0x7fffffff; }
                                }
                            } else {
                                if (d < cv[s]) {
                                    if (cv[s] < BIGF) ovfv[s] = fminf(ovfv[s], cv[s]);
                                    cv[s] = d; ck[s] = k;
                                } else {
                                    ovfv[s] = fminf(ovfv[s], d);
                                }
                            }
                        }
                    }
            }
        __syncthreads();
    }

    // ---- dump per-thread state (reuse SA region) ----
    float* Rbv = (float*)smem;
    int*   Rbk = (int*)(smem + 8192);
    float* Rcv = (float*)(smem + 16384);
    int*   Rck = (int*)(smem + 24576);
    float* Rof = (float*)(smem + 32768);
    const int cid = wn * 4 + (lane & 3);
    #pragma unroll
    for (int s = 0; s < 4; ++s) {
        int tm = s >> 1, half = s & 1;
        int m = wm * 32 + tm * 16 + (lane >> 2) + half * 8;
        int o = m * 16 + cid;
        Rbv[o] = best[s]; Rbk[o] = bk[s];
        Rcv[o] = cv[s];   Rck[o] = ck[s];
        Rof[o] = ovfv[s];
    }
    __syncthreads();

    // ---- merge per point ----
    if (tid < 128) {
        const int m = tid;
        float gb = BIGF;
        #pragma unroll
        for (int c = 0; c < 16; ++c) {
            float v = Rbv[m * 16 + c];
            if (v < gb) gb = v;
        }
        bool full = false;
        int cnt = 0, cds[16];
        #pragma unroll
        for (int c = 0; c < 16; ++c) {
            int o = m * 16 + c;
            if (Rof[o] < gb + MARGIN) full = true;
            float v = Rbv[o];
            if (v < gb + MARGIN) { if (cnt < 16) cds[cnt] = Rbk[o]; ++cnt; }
            float w = Rcv[o];
            if (w < gb + MARGIN) { if (cnt < 16) cds[cnt] = Rck[o]; ++cnt; }
        }
        if (cnt > 16) full = true;
        int n = n0 + m;
        g_An[n] = sAn[m];
        if (full) g_ccnt[n] = 100000;
        else if (cnt == 1) { g_idx[n] = cds[0]; g_ccnt[n] = 1; }
        else {
            g_ccnt[n] = cnt;
            for (int t = 0; t < cnt; ++t) g_cand[n * 16 + t] = cds[t];
        }
    }
}

// ======================= exact recheck: one warp per point =======================
__global__ void k_recheck(const float* __restrict__ z, const float* __restrict__ cb) {
    int gt = blockIdx.x * blockDim.x + threadIdx.x;
    int n = gt >> 5, lane = gt & 31;
    if (n >= NPTS) return;
    int cnt = g_ccnt[n];
    if (cnt <= 1) return;

    const float* zrow = z + (size_t)(n >> 10) * (CDIM * 1024) + (n & 1023);
    const float A = g_An[n];

    float bd = BIGF;
    int   bkk = 0x7fffffff;

    if (cnt <= 16) {
        if (lane < cnt) {
            int k = g_cand[n * 16 + lane];
            const float4* c4 = (const float4*)(cb + (size_t)k * CDIM);
            float acc = 0.f;
            #pragma unroll 4
            for (int c0 = 0; c0 < 64; ++c0) {
                float4 e = c4[c0];
                acc = fmaf(zrow[(size_t)(c0 * 4 + 0) * 1024], e.x, acc);
                acc = fmaf(zrow[(size_t)(c0 * 4 + 1) * 1024], e.y, acc);
                acc = fmaf(zrow[(size_t)(c0 * 4 + 2) * 1024], e.z, acc);
                acc = fmaf(zrow[(size_t)(c0 * 4 + 3) * 1024], e.w, acc);
            }
            bd = __fadd_rn(__fadd_rn(A, -2.0f * acc), g_cbn[k]);
            bkk = k;
        }
    } else {
        for (int k = lane; k < KCODES; k += 32) {
            const float4* c4 = (const float4*)(cb + (size_t)k * CDIM);
            float acc = 0.f;
            #pragma unroll 4
            for (int c0 = 0; c0 < 64; ++c0) {
                float4 e = c4[c0];
                acc = fmaf(zrow[(size_t)(c0 * 4 + 0) * 1024], e.x, acc);
                acc = fmaf(zrow[(size_t)(c0 * 4 + 1) * 1024], e.y, acc);
                acc = fmaf(zrow[(size_t)(c0 * 4 + 2) * 1024], e.z, acc);
                acc = fmaf(zrow[(size_t)(c0 * 4 + 3) * 1024], e.w, acc);
            }
            float d = __fadd_rn(__fadd_rn(A, -2.0f * acc), g_cbn[k]);
            if (d < bd) { bd = d; bkk = k; }
        }
    }
    #pragma unroll
    for (int off = 16; off; off >>= 1) {
        float ov = __shfl_down_sync(0xffffffffu, bd, off);
        int   ok = __shfl_down_sync(0xffffffffu, bkk, off);
        if (ov < bd || (ov == bd && ok < bkk)) { bd = ov; bkk = ok; }
    }
    if (lane == 0) g_idx[n] = bkk;
}

// ======================= histogram =======================
__global__ void k_counts() {
    int n = blockIdx.x * blockDim.x + threadIdx.x;
    if (n < NPTS) atomicAdd(&g_cnt[g_idx[n]], 1);
}

// ======================= z_q_st + loss (float4 gather) =======================
__global__ void k_zq(const float* __restrict__ z, const float* __restrict__ cb,
                     float* __restrict__ out) {
    int t = blockIdx.x * blockDim.x + threadIdx.x;   // 4,194,304 threads
    int hw = t & 1023, cg = (t >> 10) & 63, b = t >> 16;
    int n = (b << 10) | hw;
    int idx = g_idx[n];
    float4 e = ((const float4*)cb)[(size_t)idx * 64 + cg];
    size_t base = ((size_t)(b * 256 + cg * 4)) * 1024 + hw;

    double v = 0.0;
    float ev[4] = {e.x, e.y, e.z, e.w};
    #pragma unroll
    for (int j = 0; j < 4; ++j) {
        float ze = z[base + (size_t)j * 1024];
        float diff = __fsub_rn(ev[j], ze);
        out[base + (size_t)j * 1024] = __fadd_rn(ze, diff);
        v += (double)__fmul_rn(diff, diff);
    }

    #pragma unroll
    for (int off = 16; off; off >>= 1)
        v += __shfl_down_sync(0xffffffffu, v, off);
    __shared__ double ws[8];
    int lane = threadIdx.x & 31, w = threadIdx.x >> 5;
    if (lane == 0) ws[w] = v;
    __syncthreads();
    if (w == 0) {
        double s = (lane < 8) ? ws[lane] : 0.0;
        #pragma unroll
        for (int off = 4; off; off >>= 1)
            s += __shfl_down_sync(0xffffffffu, s, off);
        if (lane == 0) atomicAdd(&g_loss, s);
    }
}

// ======================= encodings: scatter 1.0f (region pre-zeroed by memset) =======================
__global__ void k_encset(float* __restrict__ out) {
    int n = blockIdx.x * blockDim.x + threadIdx.x;
    if (n < NPTS)
        out[OFF_ENC + (size_t)n * KCODES + g_idx[n]] = 1.0f;
}

// ======================= scalars =======================
__global__ void k_scalars(float* __restrict__ out) {
    __shared__ double ssum[256];
    int t = threadIdx.x;
    double s = 0.0;
    for (int k = t; k < KCODES; k += 256) {
        float em = (float)g_cnt[k] * (1.0f / 65536.0f);
        float lg = logf(__fadd_rn(em, 1e-10f));
        s += (double)__fmul_rn(em, lg);
    }
    ssum[t] = s;
    __syncthreads();
    for (int off = 128; off; off >>= 1) {
        if (t < off) ssum[t] += ssum[t + off];
        __syncthreads();
    }
    if (t == 0) {
        float S = (float)ssum[0];
        out[OFF_PERP] = expf(-S);
        double m = g_loss / 16777216.0;
        float mf = (float)m;
        out[OFF_LOSS] = __fadd_rn(mf, __fmul_rn(0.25f, mf));
    }
}

extern "C" void kernel_launch(void* const* d_in, const int* in_sizes, int n_in,
                              void* d_out, int out_size) {
    (void)out_size;
    const float* z  = (const float*)d_in[0];
    const float* cb = (const float*)d_in[1];
    if (n_in >= 2 && in_sizes[0] == KCODES * CDIM) {
        const float* t = z; z = cb; cb = t;
    }
    float* out = (float*)d_out;

    cudaFuncSetAttribute(k_argmin_mma, cudaFuncAttributeMaxDynamicSharedMemorySize, SMTOT);

    // zero the encodings region (graph-capturable memset node; overlaps later kernels' latency)
    cudaMemsetAsync(out + OFF_ENC, 0, (size_t)NPTS * KCODES * sizeof(float));

    k_prep      <<<(KCODES + 255) / 256, 256>>>(cb);          // kernel #1
    k_conv      <<<262144 / 256, 256>>>(cb);                  // kernel #2
    k_nop       <<<1, 32>>>();                                // kernel #3
    k_argmin_mma<<<NPTS / 128, TH, SMTOT>>>(z, cb);           // kernel #4 -> ncu capture
    k_recheck   <<<(NPTS * 32) / 256, 256>>>(z, cb);
    k_counts    <<<NPTS / 256, 256>>>();
    k_zq        <<<4194304 / 256, 256>>>(z, cb, out);
    k_encset    <<<NPTS / 256, 256>>>(out);
    k_scalars   <<<1, 256>>>(out);
}